// round 10
// baseline (speedup 1.0000x reference)
#include <cuda_runtime.h>
#include <math_constants.h>

// Problem constants (fixed by the dataset)
#define NN   20000      // nodes
#define EE   640000     // edges
#define HCC  128        // H * C
#define NH   4          // heads
#define CH   32         // channels per head
#define DOUT 64

// ---------------- device scratch (static: no allocations allowed) -----------
__device__ float g_XL[NN * HCC];
__device__ float g_XR[NN * HCC];
__device__ float g_H [NN * HCC];
__device__ int   g_cnt[NN];
__device__ int   g_cur[NN];
__device__ float g_asum[NN];     // sum of non-self incoming edge_attr
__device__ int   g_ascnt[NN];    // count of non-self incoming edges
__device__ int   g_rowptr[NN + 1];
__device__ int2  g_ecsr[EE];     // packed (src, edge_attr bits), CSR order by dst

// ---------------- packed fp32x2 helpers (Blackwell FFMA2 via PTX) -----------
__device__ __forceinline__ void ffma2(unsigned long long& d,
                                      unsigned long long a,
                                      unsigned long long b) {
    asm("fma.rn.f32x2 %0, %1, %2, %0;" : "+l"(d) : "l"(a), "l"(b));
}
__device__ __forceinline__ unsigned long long pack2(float x) {
    unsigned long long r;
    asm("mov.b64 %0, {%1, %1};" : "=l"(r) : "f"(x));
    return r;
}
__device__ __forceinline__ float2 unpack2(unsigned long long v) {
    float2 o;
    asm("mov.b64 {%0, %1}, %2;" : "=f"(o.x), "=f"(o.y) : "l"(v));
    return o;
}

// ---------------- CSR build ------------------------------------------------
__global__ void zero_counts_kernel() {
    int i = blockIdx.x * blockDim.x + threadIdx.x;
    if (i < NN) { g_cnt[i] = 0; g_cur[i] = 0; g_asum[i] = 0.f; g_ascnt[i] = 0; }
}

// histogram + per-dst non-self edge_attr sum/count (for fill_value='mean')
__global__ void hist_kernel(const int* __restrict__ ei,
                            const float* __restrict__ eattr, int E) {
    int e = blockIdx.x * blockDim.x + threadIdx.x;
    if (e >= E) return;
    int s = ei[e];
    int d = ei[E + e];
    if (d < 0 || d >= NN) return;
    atomicAdd(&g_cnt[d], 1);
    if (s != d) {
        atomicAdd(&g_asum[d], eattr[e]);
        atomicAdd(&g_ascnt[d], 1);
    }
}

// single-block exclusive scan of g_cnt -> g_rowptr
__global__ void scan_kernel(int n) {
    __shared__ int sums[1024];
    int tid = threadIdx.x;
    int per = (n + 1023) >> 10;
    int beg = tid * per;
    int end = beg + per;
    if (beg > n) beg = n;
    if (end > n) end = n;
    int s = 0;
    for (int i = beg; i < end; ++i) s += g_cnt[i];
    sums[tid] = s;
    __syncthreads();
    for (int off = 1; off < 1024; off <<= 1) {
        int v = (tid >= off) ? sums[tid - off] : 0;
        __syncthreads();
        sums[tid] += v;
        __syncthreads();
    }
    int run = (tid == 0) ? 0 : sums[tid - 1];
    for (int i = beg; i < end; ++i) { g_rowptr[i] = run; run += g_cnt[i]; }
    if (tid == 0) g_rowptr[n] = sums[1023];
}

__global__ void scatter_kernel(const int* __restrict__ ei,
                               const float* __restrict__ eattr, int E) {
    int e = blockIdx.x * blockDim.x + threadIdx.x;
    if (e >= E) return;
    int dst = ei[E + e];
    if (dst < 0 || dst >= NN) return;
    int pos = g_rowptr[dst] + atomicAdd(&g_cur[dst], 1);
    g_ecsr[pos] = make_int2(ei[e], __float_as_int(eattr[e]));
}

// ---------------- fused dual SGEMM (FFMA2 inner, R9 known good) -------------
__global__ __launch_bounds__(256)
void sgemm_dual_bias(const float* __restrict__ A,
                     const float* __restrict__ Bl, const float* __restrict__ Br,
                     const float* __restrict__ bl, const float* __restrict__ br,
                     float* __restrict__ CL, float* __restrict__ CR,
                     int M, int N, int K) {
    __shared__ float As [16][64];
    __shared__ float Bls[16][64];
    __shared__ float Brs[16][64];
    int tid = threadIdx.x;
    int tx = tid & 15, ty = tid >> 4;
    int bm = blockIdx.x, bn = blockIdx.y;
    int rowBase = bm * 64;

    int aRow = tid >> 2;
    int aK   = (tid & 3) * 4;
    int bK   = tid >> 4;
    int bN   = (tid & 15) * 4;

    unsigned long long accL[4][2] = {};
    unsigned long long accR[4][2] = {};

    for (int k0 = 0; k0 < K; k0 += 16) {
        float4 av;
        int gr = rowBase + aRow;
        if (gr < M) av = *(const float4*)&A[(long)gr * K + k0 + aK];
        else        av = make_float4(0.f, 0.f, 0.f, 0.f);
        As[aK + 0][aRow] = av.x;
        As[aK + 1][aRow] = av.y;
        As[aK + 2][aRow] = av.z;
        As[aK + 3][aRow] = av.w;
        long boff = (long)(k0 + bK) * N + bn * 64 + bN;
        *(float4*)&Bls[bK][bN] = *(const float4*)&Bl[boff];
        *(float4*)&Brs[bK][bN] = *(const float4*)&Br[boff];
        __syncthreads();
        #pragma unroll
        for (int kk = 0; kk < 16; ++kk) {
            float4 a4 = *(const float4*)&As[kk][ty * 4];
            ulonglong2 blp = *(const ulonglong2*)&Bls[kk][tx * 4];
            ulonglong2 brp = *(const ulonglong2*)&Brs[kk][tx * 4];
            unsigned long long ap[4];
            ap[0] = pack2(a4.x); ap[1] = pack2(a4.y);
            ap[2] = pack2(a4.z); ap[3] = pack2(a4.w);
            #pragma unroll
            for (int i = 0; i < 4; ++i) {
                ffma2(accL[i][0], ap[i], blp.x);
                ffma2(accL[i][1], ap[i], blp.y);
                ffma2(accR[i][0], ap[i], brp.x);
                ffma2(accR[i][1], ap[i], brp.y);
            }
        }
        __syncthreads();
    }
    float4 bl4 = *(const float4*)&bl[bn * 64 + tx * 4];
    float4 br4 = *(const float4*)&br[bn * 64 + tx * 4];
    #pragma unroll
    for (int i = 0; i < 4; ++i) {
        int gr = rowBase + ty * 4 + i;
        if (gr < M) {
            float2 l0 = unpack2(accL[i][0]);
            float2 l1 = unpack2(accL[i][1]);
            float2 r0 = unpack2(accR[i][0]);
            float2 r1 = unpack2(accR[i][1]);
            float4 ol, orr;
            ol.x  = l0.x + bl4.x; ol.y  = l0.y + bl4.y;
            ol.z  = l1.x + bl4.z; ol.w  = l1.y + bl4.w;
            orr.x = r0.x + br4.x; orr.y = r0.y + br4.y;
            orr.z = r1.x + br4.z; orr.w = r1.y + br4.w;
            long coff = (long)gr * N + bn * 64 + tx * 4;
            *(float4*)&CL[coff] = ol;
            *(float4*)&CR[coff] = orr;
        }
    }
}

// ---------------- single SGEMM (output projection), FFMA2 inner -------------
__global__ __launch_bounds__(256)
void sgemm_bias(const float* __restrict__ A, const float* __restrict__ B,
                const float* __restrict__ bias, float* __restrict__ C,
                int M, int N, int K) {
    __shared__ float As[16][64];
    __shared__ float Bs[16][64];
    int tid = threadIdx.x;
    int tx = tid & 15, ty = tid >> 4;
    int bm = blockIdx.x, bn = blockIdx.y;
    int rowBase = bm * 64;

    int aRow = tid >> 2;
    int aK   = (tid & 3) * 4;
    int bK   = tid >> 4;
    int bN   = (tid & 15) * 4;

    unsigned long long acc[4][2] = {};
    for (int k0 = 0; k0 < K; k0 += 16) {
        float4 av;
        int gr = rowBase + aRow;
        if (gr < M) av = *(const float4*)&A[(long)gr * K + k0 + aK];
        else        av = make_float4(0.f, 0.f, 0.f, 0.f);
        As[aK + 0][aRow] = av.x;
        As[aK + 1][aRow] = av.y;
        As[aK + 2][aRow] = av.z;
        As[aK + 3][aRow] = av.w;
        *(float4*)&Bs[bK][bN] = *(const float4*)&B[(long)(k0 + bK) * N + bn * 64 + bN];
        __syncthreads();
        #pragma unroll
        for (int kk = 0; kk < 16; ++kk) {
            float4 a4 = *(const float4*)&As[kk][ty * 4];
            ulonglong2 bp = *(const ulonglong2*)&Bs[kk][tx * 4];
            unsigned long long ap[4];
            ap[0] = pack2(a4.x); ap[1] = pack2(a4.y);
            ap[2] = pack2(a4.z); ap[3] = pack2(a4.w);
            #pragma unroll
            for (int i = 0; i < 4; ++i) {
                ffma2(acc[i][0], ap[i], bp.x);
                ffma2(acc[i][1], ap[i], bp.y);
            }
        }
        __syncthreads();
    }
    float4 bias4 = *(const float4*)&bias[bn * 64 + tx * 4];
    #pragma unroll
    for (int i = 0; i < 4; ++i) {
        int gr = rowBase + ty * 4 + i;
        if (gr < M) {
            float2 c0 = unpack2(acc[i][0]);
            float2 c1 = unpack2(acc[i][1]);
            float4 o;
            o.x = c0.x + bias4.x;
            o.y = c0.y + bias4.y;
            o.z = c1.x + bias4.z;
            o.w = c1.y + bias4.w;
            *(float4*)&C[(long)gr * N + bn * 64 + tx * 4] = o;
        }
    }
}

// ---------------- GATv2 edge phase: one warp per dst node ------------------
// Batch-4 staggered prefetch: edge descriptors 2 batches ahead, xl gathers
// 1 batch ahead — breaks the ed->xl serial dependency that exposed L2 latency.
__device__ __forceinline__ float leaky02(float m) {
    return fmaxf(m, 0.f) + 0.2f * fminf(m, 0.f);
}

__global__ __launch_bounds__(128)
void gat_edge_kernel(const float* __restrict__ XL, const float* __restrict__ XR,
                     const float* __restrict__ att, const float* __restrict__ We,
                     const float* __restrict__ bias, float* __restrict__ out,
                     int applyElu) {
    int gid  = blockIdx.x * blockDim.x + threadIdx.x;
    int n    = gid >> 5;
    int lane = gid & 31;
    if (n >= NN) return;

    int base = (lane >> 3) * CH + (lane & 7) * 4;   // head*32 + chan4
    float4 xr4 = *(const float4*)&XR[n * HCC + base];
    float4 at4 = *(const float4*)&att[base];
    float4 we4 = *(const float4*)&We[base];

    float mx = -CUDART_INF_F, dn = 0.f;
    float4 acc = make_float4(0.f, 0.f, 0.f, 0.f);

    int beg = g_rowptr[n], end = g_rowptr[n + 1];
    int last = (end > beg) ? (end - 1) : beg;       // clamp target (in-bounds)

    int2   ed0[4], ed1[4];
    float4 xl0[4];
    if (beg < end) {
        #pragma unroll
        for (int j = 0; j < 4; ++j) {
            int i0 = beg + j;     ed0[j] = g_ecsr[i0 < last ? i0 : last];
        }
        #pragma unroll
        for (int j = 0; j < 4; ++j) {
            int i1 = beg + 4 + j; ed1[j] = g_ecsr[i1 < last ? i1 : last];
        }
        #pragma unroll
        for (int j = 0; j < 4; ++j)
            xl0[j] = *(const float4*)&XL[(long)ed0[j].x * HCC + base];
    }

    for (int e = beg; e < end; e += 4) {
        // prefetch: xl for batch B+1 (descriptors already resident), ed for B+2
        float4 xl1[4];
        #pragma unroll
        for (int j = 0; j < 4; ++j)
            xl1[j] = *(const float4*)&XL[(long)ed1[j].x * HCC + base];
        int2 ed2[4];
        #pragma unroll
        for (int j = 0; j < 4; ++j) {
            int i2 = e + 8 + j;
            ed2[j] = g_ecsr[i2 < last ? i2 : last];
        }
        // process current batch
        #pragma unroll
        for (int j = 0; j < 4; ++j) {
            if (e + j >= end) break;               // warp-uniform
            int2   ed  = ed0[j];
            float4 xl4 = xl0[j];
            if (ed.x == n) continue;               // warp-uniform; PyG self-loop removal
            float ae = __int_as_float(ed.y);
            float p = leaky02(fmaf(ae, we4.x, xl4.x + xr4.x)) * at4.x
                    + leaky02(fmaf(ae, we4.y, xl4.y + xr4.y)) * at4.y
                    + leaky02(fmaf(ae, we4.z, xl4.z + xr4.z)) * at4.z
                    + leaky02(fmaf(ae, we4.w, xl4.w + xr4.w)) * at4.w;
            p += __shfl_xor_sync(0xffffffffu, p, 4);
            p += __shfl_xor_sync(0xffffffffu, p, 2);
            p += __shfl_xor_sync(0xffffffffu, p, 1);
            if (p > mx) {
                float r = __expf(mx - p);          // exp(-inf)=0 first time
                dn *= r;
                acc.x *= r; acc.y *= r; acc.z *= r; acc.w *= r;
                mx = p;
            }
            float w = __expf(p - mx);
            dn += w;
            acc.x = fmaf(w, xl4.x, acc.x);
            acc.y = fmaf(w, xl4.y, acc.y);
            acc.z = fmaf(w, xl4.z, acc.z);
            acc.w = fmaf(w, xl4.w, acc.w);
        }
        // shift pipeline
        #pragma unroll
        for (int j = 0; j < 4; ++j) {
            ed0[j] = ed1[j];
            ed1[j] = ed2[j];
            xl0[j] = xl1[j];
        }
    }

    // self loop (always added, edge_attr = mean of incoming non-self attrs)
    {
        int   c  = g_ascnt[n];
        float la = (c > 0) ? g_asum[n] / (float)c : 0.f;
        float4 xl4 = *(const float4*)&XL[n * HCC + base];
        float p = leaky02(fmaf(la, we4.x, xl4.x + xr4.x)) * at4.x
                + leaky02(fmaf(la, we4.y, xl4.y + xr4.y)) * at4.y
                + leaky02(fmaf(la, we4.z, xl4.z + xr4.z)) * at4.z
                + leaky02(fmaf(la, we4.w, xl4.w + xr4.w)) * at4.w;
        p += __shfl_xor_sync(0xffffffffu, p, 4);
        p += __shfl_xor_sync(0xffffffffu, p, 2);
        p += __shfl_xor_sync(0xffffffffu, p, 1);
        if (p > mx) {
            float r = __expf(mx - p);
            dn *= r;
            acc.x *= r; acc.y *= r; acc.z *= r; acc.w *= r;
            mx = p;
        }
        float w = __expf(p - mx);
        dn += w;
        acc.x = fmaf(w, xl4.x, acc.x);
        acc.y = fmaf(w, xl4.y, acc.y);
        acc.z = fmaf(w, xl4.z, acc.z);
        acc.w = fmaf(w, xl4.w, acc.w);
    }

    float4 b4 = *(const float4*)&bias[base];
    float inv = 1.f / dn;
    float4 o;
    o.x = fmaf(acc.x, inv, b4.x);
    o.y = fmaf(acc.y, inv, b4.y);
    o.z = fmaf(acc.z, inv, b4.z);
    o.w = fmaf(acc.w, inv, b4.w);
    if (applyElu) {
        o.x = (o.x > 0.f) ? o.x : (__expf(o.x) - 1.f);
        o.y = (o.y > 0.f) ? o.y : (__expf(o.y) - 1.f);
        o.z = (o.z > 0.f) ? o.z : (__expf(o.z) - 1.f);
        o.w = (o.w > 0.f) ? o.w : (__expf(o.w) - 1.f);
    }
    *(float4*)&out[n * HCC + base] = o;
}

// ---------------- launch ----------------------------------------------------
extern "C" void kernel_launch(void* const* d_in, const int* in_sizes, int n_in,
                              void* d_out, int out_size) {
    const float* x     = (const float*)d_in[0];
    const int*   ei    = (const int*)d_in[1];
    const float* eattr = (const float*)d_in[2];
    const float* Wl1 = (const float*)d_in[3];
    const float* bl1 = (const float*)d_in[4];
    const float* Wr1 = (const float*)d_in[5];
    const float* br1 = (const float*)d_in[6];
    const float* We1 = (const float*)d_in[7];
    const float* att1= (const float*)d_in[8];
    const float* b1  = (const float*)d_in[9];
    const float* Wl2 = (const float*)d_in[10];
    const float* bl2 = (const float*)d_in[11];
    const float* Wr2 = (const float*)d_in[12];
    const float* br2 = (const float*)d_in[13];
    const float* We2 = (const float*)d_in[14];
    const float* att2= (const float*)d_in[15];
    const float* b2  = (const float*)d_in[16];
    const float* Wo  = (const float*)d_in[17];
    const float* bo  = (const float*)d_in[18];
    float* out = (float*)d_out;

    int E = in_sizes[1] / 2;        // 640000
    int N = in_sizes[0] / HCC;      // 20000

    float *XL, *XR, *H;
    cudaGetSymbolAddress((void**)&XL, g_XL);
    cudaGetSymbolAddress((void**)&XR, g_XR);
    cudaGetSymbolAddress((void**)&H,  g_H);

    // secondary stream + events for CSR || GEMM1 overlap (host objects,
    // created once on the uncaptured correctness call, reused thereafter)
    static cudaStream_t s1 = nullptr;
    static cudaEvent_t evFork = nullptr, evJoin = nullptr;
    if (s1 == nullptr) {
        cudaStreamCreateWithFlags(&s1, cudaStreamNonBlocking);
        cudaEventCreateWithFlags(&evFork, cudaEventDisableTiming);
        cudaEventCreateWithFlags(&evJoin, cudaEventDisableTiming);
    }

    dim3 gemmGrid((N + 63) / 64, HCC / 64);
    dim3 gemmGridOut((N + 63) / 64, DOUT / 64);
    int edgeBlocks = (N * 32 + 127) / 128;   // one warp per node, 128-thr blocks
    int eBlocks    = (E + 255) / 256;
    int nBlocks    = (N + 255) / 256;

    // ---- fork: CSR build on s1, layer-1 GEMM on main stream, join before edge
    cudaEventRecord(evFork, 0);
    cudaStreamWaitEvent(s1, evFork, 0);

    zero_counts_kernel<<<nBlocks, 256, 0, s1>>>();
    hist_kernel<<<eBlocks, 256, 0, s1>>>(ei, eattr, E);
    scan_kernel<<<1, 1024, 0, s1>>>(N);
    scatter_kernel<<<eBlocks, 256, 0, s1>>>(ei, eattr, E);
    cudaEventRecord(evJoin, s1);

    sgemm_dual_bias<<<gemmGrid, 256>>>(x, Wl1, Wr1, bl1, br1, XL, XR, N, HCC, HCC);

    cudaStreamWaitEvent(0, evJoin, 0);

    // layer 1 edge phase
    gat_edge_kernel<<<edgeBlocks, 128>>>(XL, XR, att1, We1, b1, H, 1);

    // layer 2
    sgemm_dual_bias<<<gemmGrid, 256>>>(H, Wl2, Wr2, bl2, br2, XL, XR, N, HCC, HCC);
    gat_edge_kernel<<<edgeBlocks, 128>>>(XL, XR, att2, We2, b2, H, 1);

    // output projection
    sgemm_bias<<<gemmGridOut, 256>>>(H, Wo, bo, out, N, DOUT, HCC);
}

// round 11
// speedup vs baseline: 1.1509x; 1.1509x over previous
#include <cuda_runtime.h>
#include <math_constants.h>

// Problem constants (fixed by the dataset)
#define NN   20000      // nodes
#define EE   640000     // edges
#define HCC  128        // H * C
#define NH   4          // heads
#define CH   32         // channels per head
#define DOUT 64

// ---------------- device scratch (static: no allocations allowed) -----------
__device__ float g_XL[NN * HCC];
__device__ float g_XR[NN * HCC];
__device__ float g_H [NN * HCC];
__device__ int   g_cnt[NN];
__device__ int   g_cur[NN];
__device__ float g_asum[NN];     // sum of non-self incoming edge_attr
__device__ int   g_ascnt[NN];    // count of non-self incoming edges
__device__ int   g_rowptr[NN + 1];
__device__ int2  g_ecsr[EE];     // packed (src, edge_attr bits), CSR order by dst

// ---------------- packed fp32x2 helpers (Blackwell FFMA2 via PTX) -----------
__device__ __forceinline__ void ffma2(unsigned long long& d,
                                      unsigned long long a,
                                      unsigned long long b) {
    asm("fma.rn.f32x2 %0, %1, %2, %0;" : "+l"(d) : "l"(a), "l"(b));
}
__device__ __forceinline__ unsigned long long pack2(float x) {
    unsigned long long r;
    asm("mov.b64 %0, {%1, %1};" : "=l"(r) : "f"(x));
    return r;
}
__device__ __forceinline__ float2 unpack2(unsigned long long v) {
    float2 o;
    asm("mov.b64 {%0, %1}, %2;" : "=f"(o.x), "=f"(o.y) : "l"(v));
    return o;
}

// ---------------- CSR build ------------------------------------------------
__global__ void zero_counts_kernel() {
    int i = blockIdx.x * blockDim.x + threadIdx.x;
    if (i < NN) { g_cnt[i] = 0; g_cur[i] = 0; g_asum[i] = 0.f; g_ascnt[i] = 0; }
}

// histogram + per-dst non-self edge_attr sum/count; grid-stride x2 for MLP
__global__ void hist_kernel(const int* __restrict__ ei,
                            const float* __restrict__ eattr, int E) {
    int stride = gridDim.x * blockDim.x;
    for (int e = blockIdx.x * blockDim.x + threadIdx.x; e < E; e += stride) {
        int s = ei[e];
        int d = ei[E + e];
        if (d < 0 || d >= NN) continue;
        atomicAdd(&g_cnt[d], 1);
        if (s != d) {
            atomicAdd(&g_asum[d], eattr[e]);
            atomicAdd(&g_ascnt[d], 1);
        }
    }
}

// single-block exclusive scan of g_cnt -> g_rowptr
__global__ void scan_kernel(int n) {
    __shared__ int sums[1024];
    int tid = threadIdx.x;
    int per = (n + 1023) >> 10;
    int beg = tid * per;
    int end = beg + per;
    if (beg > n) beg = n;
    if (end > n) end = n;
    int s = 0;
    for (int i = beg; i < end; ++i) s += g_cnt[i];
    sums[tid] = s;
    __syncthreads();
    for (int off = 1; off < 1024; off <<= 1) {
        int v = (tid >= off) ? sums[tid - off] : 0;
        __syncthreads();
        sums[tid] += v;
        __syncthreads();
    }
    int run = (tid == 0) ? 0 : sums[tid - 1];
    for (int i = beg; i < end; ++i) { g_rowptr[i] = run; run += g_cnt[i]; }
    if (tid == 0) g_rowptr[n] = sums[1023];
}

__global__ void scatter_kernel(const int* __restrict__ ei,
                               const float* __restrict__ eattr, int E) {
    int stride = gridDim.x * blockDim.x;
    for (int e = blockIdx.x * blockDim.x + threadIdx.x; e < E; e += stride) {
        int dst = ei[E + e];
        if (dst < 0 || dst >= NN) continue;
        int pos = g_rowptr[dst] + atomicAdd(&g_cur[dst], 1);
        g_ecsr[pos] = make_int2(ei[e], __float_as_int(eattr[e]));
    }
}

// ---------------- fused dual SGEMM (FFMA2 inner, R9 known good) -------------
__global__ __launch_bounds__(256)
void sgemm_dual_bias(const float* __restrict__ A,
                     const float* __restrict__ Bl, const float* __restrict__ Br,
                     const float* __restrict__ bl, const float* __restrict__ br,
                     float* __restrict__ CL, float* __restrict__ CR,
                     int M, int N, int K) {
    __shared__ float As [16][64];
    __shared__ float Bls[16][64];
    __shared__ float Brs[16][64];
    int tid = threadIdx.x;
    int tx = tid & 15, ty = tid >> 4;
    int bm = blockIdx.x, bn = blockIdx.y;
    int rowBase = bm * 64;

    int aRow = tid >> 2;
    int aK   = (tid & 3) * 4;
    int bK   = tid >> 4;
    int bN   = (tid & 15) * 4;

    unsigned long long accL[4][2] = {};
    unsigned long long accR[4][2] = {};

    for (int k0 = 0; k0 < K; k0 += 16) {
        float4 av;
        int gr = rowBase + aRow;
        if (gr < M) av = *(const float4*)&A[(long)gr * K + k0 + aK];
        else        av = make_float4(0.f, 0.f, 0.f, 0.f);
        As[aK + 0][aRow] = av.x;
        As[aK + 1][aRow] = av.y;
        As[aK + 2][aRow] = av.z;
        As[aK + 3][aRow] = av.w;
        long boff = (long)(k0 + bK) * N + bn * 64 + bN;
        *(float4*)&Bls[bK][bN] = *(const float4*)&Bl[boff];
        *(float4*)&Brs[bK][bN] = *(const float4*)&Br[boff];
        __syncthreads();
        #pragma unroll
        for (int kk = 0; kk < 16; ++kk) {
            float4 a4 = *(const float4*)&As[kk][ty * 4];
            ulonglong2 blp = *(const ulonglong2*)&Bls[kk][tx * 4];
            ulonglong2 brp = *(const ulonglong2*)&Brs[kk][tx * 4];
            unsigned long long ap[4];
            ap[0] = pack2(a4.x); ap[1] = pack2(a4.y);
            ap[2] = pack2(a4.z); ap[3] = pack2(a4.w);
            #pragma unroll
            for (int i = 0; i < 4; ++i) {
                ffma2(accL[i][0], ap[i], blp.x);
                ffma2(accL[i][1], ap[i], blp.y);
                ffma2(accR[i][0], ap[i], brp.x);
                ffma2(accR[i][1], ap[i], brp.y);
            }
        }
        __syncthreads();
    }
    float4 bl4 = *(const float4*)&bl[bn * 64 + tx * 4];
    float4 br4 = *(const float4*)&br[bn * 64 + tx * 4];
    #pragma unroll
    for (int i = 0; i < 4; ++i) {
        int gr = rowBase + ty * 4 + i;
        if (gr < M) {
            float2 l0 = unpack2(accL[i][0]);
            float2 l1 = unpack2(accL[i][1]);
            float2 r0 = unpack2(accR[i][0]);
            float2 r1 = unpack2(accR[i][1]);
            float4 ol, orr;
            ol.x  = l0.x + bl4.x; ol.y  = l0.y + bl4.y;
            ol.z  = l1.x + bl4.z; ol.w  = l1.y + bl4.w;
            orr.x = r0.x + br4.x; orr.y = r0.y + br4.y;
            orr.z = r1.x + br4.z; orr.w = r1.y + br4.w;
            long coff = (long)gr * N + bn * 64 + tx * 4;
            *(float4*)&CL[coff] = ol;
            *(float4*)&CR[coff] = orr;
        }
    }
}

// ---------------- single SGEMM (output projection), FFMA2 inner -------------
__global__ __launch_bounds__(256)
void sgemm_bias(const float* __restrict__ A, const float* __restrict__ B,
                const float* __restrict__ bias, float* __restrict__ C,
                int M, int N, int K) {
    __shared__ float As[16][64];
    __shared__ float Bs[16][64];
    int tid = threadIdx.x;
    int tx = tid & 15, ty = tid >> 4;
    int bm = blockIdx.x, bn = blockIdx.y;
    int rowBase = bm * 64;

    int aRow = tid >> 2;
    int aK   = (tid & 3) * 4;
    int bK   = tid >> 4;
    int bN   = (tid & 15) * 4;

    unsigned long long acc[4][2] = {};
    for (int k0 = 0; k0 < K; k0 += 16) {
        float4 av;
        int gr = rowBase + aRow;
        if (gr < M) av = *(const float4*)&A[(long)gr * K + k0 + aK];
        else        av = make_float4(0.f, 0.f, 0.f, 0.f);
        As[aK + 0][aRow] = av.x;
        As[aK + 1][aRow] = av.y;
        As[aK + 2][aRow] = av.z;
        As[aK + 3][aRow] = av.w;
        *(float4*)&Bs[bK][bN] = *(const float4*)&B[(long)(k0 + bK) * N + bn * 64 + bN];
        __syncthreads();
        #pragma unroll
        for (int kk = 0; kk < 16; ++kk) {
            float4 a4 = *(const float4*)&As[kk][ty * 4];
            ulonglong2 bp = *(const ulonglong2*)&Bs[kk][tx * 4];
            unsigned long long ap[4];
            ap[0] = pack2(a4.x); ap[1] = pack2(a4.y);
            ap[2] = pack2(a4.z); ap[3] = pack2(a4.w);
            #pragma unroll
            for (int i = 0; i < 4; ++i) {
                ffma2(acc[i][0], ap[i], bp.x);
                ffma2(acc[i][1], ap[i], bp.y);
            }
        }
        __syncthreads();
    }
    float4 bias4 = *(const float4*)&bias[bn * 64 + tx * 4];
    #pragma unroll
    for (int i = 0; i < 4; ++i) {
        int gr = rowBase + ty * 4 + i;
        if (gr < M) {
            float2 c0 = unpack2(acc[i][0]);
            float2 c1 = unpack2(acc[i][1]);
            float4 o;
            o.x = c0.x + bias4.x;
            o.y = c0.y + bias4.y;
            o.z = c1.x + bias4.z;
            o.w = c1.y + bias4.w;
            *(float4*)&C[(long)gr * N + bn * 64 + tx * 4] = o;
        }
    }
}

// ---------------- GATv2 edge phase: one warp per dst node ------------------
// R9 structure; edge descriptors held 2 ahead so the xl gather for e+1 never
// waits on its own descriptor load. One clamped redundant gather per node max.
__device__ __forceinline__ float leaky02(float m) {
    return fmaxf(m, 0.f) + 0.2f * fminf(m, 0.f);
}

__global__ __launch_bounds__(256)
void gat_edge_kernel(const float* __restrict__ XL, const float* __restrict__ XR,
                     const float* __restrict__ att, const float* __restrict__ We,
                     const float* __restrict__ bias, float* __restrict__ out,
                     int applyElu) {
    int gid  = blockIdx.x * blockDim.x + threadIdx.x;
    int n    = gid >> 5;
    int lane = gid & 31;
    if (n >= NN) return;

    int base = (lane >> 3) * CH + (lane & 7) * 4;   // head*32 + chan4
    float4 xr4 = *(const float4*)&XR[n * HCC + base];
    float4 at4 = *(const float4*)&att[base];
    float4 we4 = *(const float4*)&We[base];

    float mx = -CUDART_INF_F, dn = 0.f;
    float4 acc = make_float4(0.f, 0.f, 0.f, 0.f);

    int beg = g_rowptr[n], end = g_rowptr[n + 1];

    int2   edC = make_int2(0, 0), edN = make_int2(0, 0);
    float4 xlC = make_float4(0.f, 0.f, 0.f, 0.f);
    int last = end - 1;
    if (beg < end) {
        edC = g_ecsr[beg];
        edN = g_ecsr[(beg + 1 < end) ? (beg + 1) : last];
        xlC = *(const float4*)&XL[(long)edC.x * HCC + base];
    }

    for (int e = beg; e < end; ++e) {
        // issue next-edge gather immediately (descriptor already resident)
        float4 xlN = *(const float4*)&XL[(long)edN.x * HCC + base];
        int i2 = e + 2;
        int2 edNN = g_ecsr[(i2 < end) ? i2 : last];
        // process current edge
        if (edC.x != n) {                           // PyG self-loop removal
            float ae = __int_as_float(edC.y);
            float p = leaky02(fmaf(ae, we4.x, xlC.x + xr4.x)) * at4.x
                    + leaky02(fmaf(ae, we4.y, xlC.y + xr4.y)) * at4.y
                    + leaky02(fmaf(ae, we4.z, xlC.z + xr4.z)) * at4.z
                    + leaky02(fmaf(ae, we4.w, xlC.w + xr4.w)) * at4.w;
            p += __shfl_xor_sync(0xffffffffu, p, 4);
            p += __shfl_xor_sync(0xffffffffu, p, 2);
            p += __shfl_xor_sync(0xffffffffu, p, 1);
            if (p > mx) {
                float r = __expf(mx - p);           // exp(-inf)=0 first time
                dn *= r;
                acc.x *= r; acc.y *= r; acc.z *= r; acc.w *= r;
                mx = p;
            }
            float w = __expf(p - mx);
            dn += w;
            acc.x = fmaf(w, xlC.x, acc.x);
            acc.y = fmaf(w, xlC.y, acc.y);
            acc.z = fmaf(w, xlC.z, acc.z);
            acc.w = fmaf(w, xlC.w, acc.w);
        }
        edC = edN; edN = edNN; xlC = xlN;
    }

    // self loop (always added, edge_attr = mean of incoming non-self attrs)
    {
        int   c  = g_ascnt[n];
        float la = (c > 0) ? g_asum[n] / (float)c : 0.f;
        float4 xl4 = *(const float4*)&XL[n * HCC + base];
        float p = leaky02(fmaf(la, we4.x, xl4.x + xr4.x)) * at4.x
                + leaky02(fmaf(la, we4.y, xl4.y + xr4.y)) * at4.y
                + leaky02(fmaf(la, we4.z, xl4.z + xr4.z)) * at4.z
                + leaky02(fmaf(la, we4.w, xl4.w + xr4.w)) * at4.w;
        p += __shfl_xor_sync(0xffffffffu, p, 4);
        p += __shfl_xor_sync(0xffffffffu, p, 2);
        p += __shfl_xor_sync(0xffffffffu, p, 1);
        if (p > mx) {
            float r = __expf(mx - p);
            dn *= r;
            acc.x *= r; acc.y *= r; acc.z *= r; acc.w *= r;
            mx = p;
        }
        float w = __expf(p - mx);
        dn += w;
        acc.x = fmaf(w, xl4.x, acc.x);
        acc.y = fmaf(w, xl4.y, acc.y);
        acc.z = fmaf(w, xl4.z, acc.z);
        acc.w = fmaf(w, xl4.w, acc.w);
    }

    float4 b4 = *(const float4*)&bias[base];
    float inv = 1.f / dn;
    float4 o;
    o.x = fmaf(acc.x, inv, b4.x);
    o.y = fmaf(acc.y, inv, b4.y);
    o.z = fmaf(acc.z, inv, b4.z);
    o.w = fmaf(acc.w, inv, b4.w);
    if (applyElu) {
        o.x = (o.x > 0.f) ? o.x : (__expf(o.x) - 1.f);
        o.y = (o.y > 0.f) ? o.y : (__expf(o.y) - 1.f);
        o.z = (o.z > 0.f) ? o.z : (__expf(o.z) - 1.f);
        o.w = (o.w > 0.f) ? o.w : (__expf(o.w) - 1.f);
    }
    *(float4*)&out[n * HCC + base] = o;
}

// ---------------- launch ----------------------------------------------------
extern "C" void kernel_launch(void* const* d_in, const int* in_sizes, int n_in,
                              void* d_out, int out_size) {
    const float* x     = (const float*)d_in[0];
    const int*   ei    = (const int*)d_in[1];
    const float* eattr = (const float*)d_in[2];
    const float* Wl1 = (const float*)d_in[3];
    const float* bl1 = (const float*)d_in[4];
    const float* Wr1 = (const float*)d_in[5];
    const float* br1 = (const float*)d_in[6];
    const float* We1 = (const float*)d_in[7];
    const float* att1= (const float*)d_in[8];
    const float* b1  = (const float*)d_in[9];
    const float* Wl2 = (const float*)d_in[10];
    const float* bl2 = (const float*)d_in[11];
    const float* Wr2 = (const float*)d_in[12];
    const float* br2 = (const float*)d_in[13];
    const float* We2 = (const float*)d_in[14];
    const float* att2= (const float*)d_in[15];
    const float* b2  = (const float*)d_in[16];
    const float* Wo  = (const float*)d_in[17];
    const float* bo  = (const float*)d_in[18];
    float* out = (float*)d_out;

    int E = in_sizes[1] / 2;        // 640000
    int N = in_sizes[0] / HCC;      // 20000

    float *XL, *XR, *H;
    cudaGetSymbolAddress((void**)&XL, g_XL);
    cudaGetSymbolAddress((void**)&XR, g_XR);
    cudaGetSymbolAddress((void**)&H,  g_H);

    // secondary stream + events for CSR || GEMM1 overlap (host objects,
    // created once on the uncaptured correctness call, reused thereafter)
    static cudaStream_t s1 = nullptr;
    static cudaEvent_t evFork = nullptr, evJoin = nullptr;
    if (s1 == nullptr) {
        cudaStreamCreateWithFlags(&s1, cudaStreamNonBlocking);
        cudaEventCreateWithFlags(&evFork, cudaEventDisableTiming);
        cudaEventCreateWithFlags(&evJoin, cudaEventDisableTiming);
    }

    dim3 gemmGrid((N + 63) / 64, HCC / 64);
    dim3 gemmGridOut((N + 63) / 64, DOUT / 64);
    int edgeBlocks = (N * 32 + 255) / 256;   // one warp per node
    int eBlocks2   = (E / 2 + 255) / 256;    // grid-stride x2 (MLP)
    int nBlocks    = (N + 255) / 256;

    // ---- fork: CSR build on s1, layer-1 GEMM on main stream, join before edge
    cudaEventRecord(evFork, 0);
    cudaStreamWaitEvent(s1, evFork, 0);

    zero_counts_kernel<<<nBlocks, 256, 0, s1>>>();
    hist_kernel<<<eBlocks2, 256, 0, s1>>>(ei, eattr, E);
    scan_kernel<<<1, 1024, 0, s1>>>(N);
    scatter_kernel<<<eBlocks2, 256, 0, s1>>>(ei, eattr, E);
    cudaEventRecord(evJoin, s1);

    sgemm_dual_bias<<<gemmGrid, 256>>>(x, Wl1, Wr1, bl1, br1, XL, XR, N, HCC, HCC);

    cudaStreamWaitEvent(0, evJoin, 0);

    // layer 1 edge phase
    gat_edge_kernel<<<edgeBlocks, 256>>>(XL, XR, att1, We1, b1, H, 1);

    // layer 2
    sgemm_dual_bias<<<gemmGrid, 256>>>(H, Wl2, Wr2, bl2, br2, XL, XR, N, HCC, HCC);
    gat_edge_kernel<<<edgeBlocks, 256>>>(XL, XR, att2, We2, b2, H, 1);

    // output projection
    sgemm_bias<<<gemmGridOut, 256>>>(H, Wo, bo, out, N, DOUT, HCC);
}